// round 3
// baseline (speedup 1.0000x reference)
#include <cuda_runtime.h>
#include <math.h>

#define NMAX 40000
#define EMAX 640000
#define DD   128
#define HH   8
#define DKK  16
#define TT   3
#define RR   4
#define NPB  32              // nodes per proj/final block
#define XPAD 34              // padded smem row stride (words)
#define N4   (NMAX * RR)

// ---------------- scratch (device globals) ------------------------------------
__device__ float g_k   [NMAX * DD];
__device__ float g_v   [NMAX * DD];
__device__ float g_qt  [NMAX * RR * DD];
__device__ float g_sp  [NMAX * DD];
__device__ float g_aggr[NMAX * DD];
__device__ float g_Wsp [DD * DD];
__device__ float g_bsp [DD];
__device__ int   g_win [NMAX];
__device__ int   g_thist[N4];
__device__ int   g_toff [N4 + 1];
__device__ int   g_tcur [N4];
__device__ int   g_epack[EMAX];
__device__ int   g_bsum [256];
__device__ int   g_typehist[TT];
__device__ int   g_typecur [TT];
__device__ int   g_perm [NMAX];

// ---------------- packed f32x2 helpers ----------------------------------------
__device__ __forceinline__ unsigned long long pack2(float a, float b) {
    unsigned long long r;
    asm("mov.b64 %0, {%1, %2};" : "=l"(r) : "f"(a), "f"(b));
    return r;
}
__device__ __forceinline__ void unpack2(unsigned long long v, float& lo, float& hi) {
    asm("mov.b64 {%0, %1}, %2;" : "=f"(lo), "=f"(hi) : "l"(v));
}
__device__ __forceinline__ void fma2(unsigned long long& acc,
                                     unsigned long long x, unsigned long long w) {
    asm("fma.rn.f32x2 %0, %1, %2, %0;" : "+l"(acc) : "l"(x), "l"(w));
}

// ------------------ init: zero hists + precompute Wsp = Vw[1]@s2u --------------
__global__ void k_init(const float* __restrict__ Vw, const float* __restrict__ Vb,
                       const float* __restrict__ s2u, int n, int zb) {
    if ((int)blockIdx.x < zb) {
        int i = blockIdx.x * 256 + threadIdx.x;
        if (i < n) g_win[i] = -1;
        if (i < 4 * n) g_thist[i] = 0;
        if (i < TT) { g_typehist[i] = 0; g_typecur[i] = 0; }
    } else {
        int bi  = blockIdx.x - zb;
        int row = bi * 2 + (threadIdx.x >> 7);
        int d   = threadIdx.x & 127;
        if (row < DD) {
            float acc = 0.f;
            for (int m = 0; m < DD; m++)
                acc += Vw[(DD + row) * DD + m] * s2u[m * DD + d];
            g_Wsp[row * DD + d] = acc;
        } else if (row == DD) {
            float acc = 0.f;
            for (int m = 0; m < DD; m++)
                acc += Vb[DD + m] * s2u[m * DD + d];
            g_bsp[d] = acc;
        }
    }
}

__global__ void k_nodehist(const int* __restrict__ ntype, int n) {
    int i = blockIdx.x * blockDim.x + threadIdx.x;
    if (i < n) atomicAdd(&g_typehist[ntype[i]], 1);
}

__global__ void k_nodescatter(const int* __restrict__ ntype, int n) {
    int i = blockIdx.x * blockDim.x + threadIdx.x;
    if (i >= n) return;
    int t = ntype[i];
    int off = 0;
    for (int ty = 0; ty < TT; ty++) if (ty < t) off += g_typehist[ty];
    int pos = off + atomicAdd(&g_typecur[t], 1);
    g_perm[pos] = i;
}

// ----- projections (K,Q,V,speaker) + per-relation Q transforms, f32x2 ---------
__global__ void __launch_bounds__(256)
k_proj(const float* __restrict__ x, const int* __restrict__ ntype,
       const float* __restrict__ Kw, const float* __restrict__ Kb,
       const float* __restrict__ Qw, const float* __restrict__ Qb,
       const float* __restrict__ Vw, const float* __restrict__ Vb,
       const float* __restrict__ Ratt, int n) {
    __shared__ __align__(16) float xsT[DD][XPAD];   // [feature][node]
    __shared__ __align__(16) float qsT[DD][XPAD];
    __shared__ int nodes_s[NPB], types_s[NPB];
    int tid  = threadIdx.x;
    int base = blockIdx.x * NPB;
    if (tid < NPB) {
        int idx = base + tid;
        int cidx = (idx < n) ? idx : (n - 1);
        nodes_s[tid] = (idx < n) ? g_perm[idx] : -1;
        types_s[tid] = ntype[g_perm[cidx]];
    }
    __syncthreads();
    // cooperative transposed load of x
    for (int idx = tid; idx < NPB * DD; idx += 256) {
        int j = idx >> 7;
        int k = idx & 127;
        int nd = nodes_s[j];
        xsT[k][j] = (nd >= 0) ? x[nd * DD + k] : 0.f;
    }
    __syncthreads();

    int g  = tid >> 7;      // group 0/1 -> 16 nodes each
    int d  = tid & 127;
    int jb = g * 16;

    int t0 = types_s[jb];
    bool uniform = true;
#pragma unroll
    for (int j = 1; j < 16; j++) uniform &= (types_s[jb + j] == t0);

    if (uniform) {
        const float* KwT = Kw + t0 * DD * DD;
        const float* QwT = Qw + t0 * DD * DD;
        const float* VwT = Vw + t0 * DD * DD;
        float bK = Kb[t0 * DD + d], bQ = Qb[t0 * DD + d];
        float bV = Vb[t0 * DD + d], bS = g_bsp[d];
        unsigned long long aK[8], aQ[8], aV[8], aS[8];
#pragma unroll
        for (int p = 0; p < 8; p++) {
            aK[p] = pack2(bK, bK); aQ[p] = pack2(bQ, bQ);
            aV[p] = pack2(bV, bV); aS[p] = pack2(bS, bS);
        }
#pragma unroll 2
        for (int k = 0; k < DD; k++) {
            unsigned long long wk = pack2(KwT[k * DD + d], KwT[k * DD + d]);
            unsigned long long wq = pack2(QwT[k * DD + d], QwT[k * DD + d]);
            unsigned long long wv = pack2(VwT[k * DD + d], VwT[k * DD + d]);
            float ws = g_Wsp[k * DD + d];
            unsigned long long w2 = pack2(ws, ws);
#pragma unroll
            for (int p = 0; p < 8; p++) {
                unsigned long long xp =
                    *(const unsigned long long*)&xsT[k][jb + 2 * p];
                fma2(aK[p], xp, wk);
                fma2(aQ[p], xp, wq);
                fma2(aV[p], xp, wv);
                fma2(aS[p], xp, w2);
            }
        }
#pragma unroll
        for (int p = 0; p < 8; p++) {
            int j0 = jb + 2 * p;
            int n0 = nodes_s[j0], n1 = nodes_s[j0 + 1];
            float lo, hi;
            unpack2(aK[p], lo, hi);
            if (n0 >= 0) g_k[n0 * DD + d] = lo;
            if (n1 >= 0) g_k[n1 * DD + d] = hi;
            unpack2(aV[p], lo, hi);
            if (n0 >= 0) g_v[n0 * DD + d] = lo;
            if (n1 >= 0) g_v[n1 * DD + d] = hi;
            unpack2(aS[p], lo, hi);
            if (n0 >= 0) g_sp[n0 * DD + d] = lo;
            if (n1 >= 0) g_sp[n1 * DD + d] = hi;
            unpack2(aQ[p], lo, hi);
            *(float2*)&qsT[d][j0] = make_float2(lo, hi);
        }
    } else {
        // rare boundary block: scalar per node
        for (int j = 0; j < 16; j++) {
            int nd = nodes_s[jb + j];
            int t  = types_s[jb + j];
            float aK = Kb[t * DD + d], aQ = Qb[t * DD + d];
            float aV = Vb[t * DD + d], aS = g_bsp[d];
            for (int k = 0; k < DD; k++) {
                float xv = xsT[k][jb + j];
                aK += xv * Kw[(t * DD + k) * DD + d];
                aQ += xv * Qw[(t * DD + k) * DD + d];
                aV += xv * Vw[(t * DD + k) * DD + d];
                aS += xv * g_Wsp[k * DD + d];
            }
            if (nd >= 0) {
                g_k [nd * DD + d] = aK;
                g_v [nd * DD + d] = aV;
                g_sp[nd * DD + d] = aS;
            }
            qsT[d][jb + j] = aQ;
        }
    }
    __syncthreads();

    // q' per relation: qt(h,dk) = sum_f q(h,f) * Ratt[r,h,dk,f]  (packed pairs)
    int h = d >> 4, dk = d & 15;
    for (int r = 0; r < RR; r++) {
        unsigned long long ar2[DKK];
#pragma unroll
        for (int f = 0; f < DKK; f++) {
            float a = Ratt[((r * HH + h) * DKK + dk) * DKK + f];
            ar2[f] = pack2(a, a);
        }
#pragma unroll
        for (int p = 0; p < 8; p++) {
            int j0 = jb + 2 * p;
            unsigned long long acc = pack2(0.f, 0.f);
#pragma unroll
            for (int f = 0; f < DKK; f++) {
                unsigned long long qp =
                    *(const unsigned long long*)&qsT[(h << 4) + f][j0];
                fma2(acc, qp, ar2[f]);
            }
            float lo, hi;
            unpack2(acc, lo, hi);
            int n0 = nodes_s[j0], n1 = nodes_s[j0 + 1];
            if (n0 >= 0) g_qt[(n0 * RR + r) * DD + d] = lo;
            if (n1 >= 0) g_qt[(n1 * RR + r) * DD + d] = hi;
        }
    }
}

// ------------------------------ edge setup ------------------------------------
__global__ void k_edgestats(const int* __restrict__ ei, const int* __restrict__ et, int e) {
    int i = blockIdx.x * blockDim.x + threadIdx.x;
    if (i >= e) return;
    int tgt = ei[e + i];
    int r   = et[i];
    atomicAdd(&g_thist[tgt * RR + r], 1);
    if (r == 0) atomicMax(&g_win[ei[i]], i);
}

__global__ void k_scan1(int n4) {
    __shared__ int buf[1024];
    int t = threadIdx.x;
    int gid = blockIdx.x * 1024 + t;
    int v = (gid < n4) ? g_thist[gid] : 0;
    buf[t] = v;
    __syncthreads();
    for (int off = 1; off < 1024; off <<= 1) {
        int x = (t >= off) ? buf[t - off] : 0;
        __syncthreads();
        buf[t] += x;
        __syncthreads();
    }
    if (gid < n4) g_toff[gid] = buf[t] - v;
    if (t == 1023) g_bsum[blockIdx.x] = buf[t];
}

__global__ void k_scan2(int nblocks, int n4) {
    if (threadIdx.x == 0) {
        int run = 0;
        for (int b = 0; b < nblocks; b++) { int x = g_bsum[b]; g_bsum[b] = run; run += x; }
        g_toff[n4] = run;
    }
}

__global__ void k_scan3(int n4) {
    int gid = blockIdx.x * blockDim.x + threadIdx.x;
    if (gid < n4) {
        int v = g_toff[gid] + g_bsum[gid >> 10];
        g_toff[gid] = v;
        g_tcur[gid] = v;
    }
}

__global__ void k_scatter_edges(const int* __restrict__ ei, const int* __restrict__ et,
                                const int* __restrict__ ntype, int e) {
    int i = blockIdx.x * blockDim.x + threadIdx.x;
    if (i >= e) return;
    int src = ei[i];
    int tgt = ei[e + i];
    int r   = et[i];
    int st  = ntype[src];
    int pos = atomicAdd(&g_tcur[tgt * RR + r], 1);
    g_epack[pos] = src | (st << 16);
}

// ------- attention: warp per target, per-relation sub-loops --------------------
__global__ void __launch_bounds__(256)
k_attn(const int* __restrict__ ntype, const float* __restrict__ pri,
       const float* __restrict__ Rmsg, int n) {
    __shared__ float accsh[8][RR][DD];
    int warp = threadIdx.x >> 5, lane = threadIdx.x & 31;
    int i = blockIdx.x * 8 + warp;
    if (i >= n) return;
    int d0 = lane * 4;
    int h  = lane >> 2;

    int tt = ntype[i];
    float p0[TT], p1[TT], p2[TT], p3[TT];
#pragma unroll
    for (int st = 0; st < TT; st++) {
        p0[st] = pri[((tt * RR + 0) * TT + st) * HH + h];
        p1[st] = pri[((tt * RR + 1) * TT + st) * HH + h];
        p2[st] = pri[((tt * RR + 2) * TT + st) * HH + h];
        p3[st] = pri[((tt * RR + 3) * TT + st) * HH + h];
    }

    float den = 0.f;
    float4 acc[RR];
#pragma unroll
    for (int r = 0; r < RR; r++) acc[r] = make_float4(0.f, 0.f, 0.f, 0.f);

#pragma unroll
    for (int r = 0; r < RR; r++) {
        int beg = g_toff[i * RR + r], end = g_toff[i * RR + r + 1];
        if (beg == end) continue;
        float4 qtr = *(const float4*)&g_qt[(i * RR + r) * DD + d0];
        float4 a = make_float4(0.f, 0.f, 0.f, 0.f);
        for (int idx = beg; idx < end; idx++) {
            int pk  = g_epack[idx];
            int src = pk & 0xFFFF;
            int st  = pk >> 16;
            const float4 k4 = *(const float4*)&g_k[src * DD + d0];
            float s = qtr.x * k4.x + qtr.y * k4.y + qtr.z * k4.z + qtr.w * k4.w;
            s += __shfl_xor_sync(0xffffffffu, s, 1);
            s += __shfl_xor_sync(0xffffffffu, s, 2);
            float pr = (r == 0) ? p0[0] : (r == 1) ? p1[0] : (r == 2) ? p2[0] : p3[0];
            if (st == 1) pr = (r == 0) ? p0[1] : (r == 1) ? p1[1] : (r == 2) ? p2[1] : p3[1];
            if (st == 2) pr = (r == 0) ? p0[2] : (r == 1) ? p1[2] : (r == 2) ? p2[2] : p3[2];
            float pe = __expf(s * pr * 0.25f);
            den += pe;
            const float4 v4 = *(const float4*)&g_v[src * DD + d0];
            a.x += pe * v4.x;
            a.y += pe * v4.y;
            a.z += pe * v4.z;
            a.w += pe * v4.w;
        }
        acc[r] = a;
    }

    float inv = 1.f / (den + 1e-16f);
#pragma unroll
    for (int r = 0; r < RR; r++) {
        accsh[warp][r][d0 + 0] = acc[r].x * inv;
        accsh[warp][r][d0 + 1] = acc[r].y * inv;
        accsh[warp][r][d0 + 2] = acc[r].z * inv;
        accsh[warp][r][d0 + 3] = acc[r].w * inv;
    }
    __syncwarp();

    int f0 = (lane & 3) * 4;
    float4 o = make_float4(0.f, 0.f, 0.f, 0.f);
#pragma unroll
    for (int r = 0; r < RR; r++) {
#pragma unroll 4
        for (int dk = 0; dk < DKK; dk++) {
            float a = accsh[warp][r][(h << 4) + dk];
            const float4 w = *(const float4*)&Rmsg[(((r * HH + h) * DKK + dk) * DKK) + f0];
            o.x += a * w.x;
            o.y += a * w.y;
            o.z += a * w.z;
            o.w += a * w.w;
        }
    }
    *(float4*)&g_aggr[i * DD + d0] = o;
}

// ------------- final: speaker add + GELU + per-type A projection + skip -------
__global__ void __launch_bounds__(256)
k_final(const float* __restrict__ x, const int* __restrict__ ntype,
        const int* __restrict__ ei,
        const float* __restrict__ Aw, const float* __restrict__ Ab,
        const float* __restrict__ skip, float* __restrict__ out, int n, int e) {
    __shared__ __align__(16) float gsT[DD][XPAD];
    __shared__ int nodes_s[NPB], types_s[NPB], spsrc_s[NPB];
    int tid  = threadIdx.x;
    int base = blockIdx.x * NPB;
    if (tid < NPB) {
        int idx = base + tid;
        int cidx = (idx < n) ? idx : (n - 1);
        int nd = (idx < n) ? g_perm[idx] : -1;
        nodes_s[tid] = nd;
        types_s[tid] = ntype[g_perm[cidx]];
        int sps = -1;
        if (nd >= 0) {
            int we = g_win[nd];
            if (we >= 0) sps = ei[e + we];
        }
        spsrc_s[tid] = sps;
    }
    __syncthreads();

    for (int idx = tid; idx < NPB * DD; idx += 256) {
        int j = idx >> 7;
        int k = idx & 127;
        int nd = nodes_s[j];
        float v = 0.f;
        if (nd >= 0) {
            v = g_aggr[nd * DD + k];
            int sps = spsrc_s[j];
            if (sps >= 0) v += g_sp[sps * DD + k];
            v = 0.5f * v * (1.f + erff(v * 0.70710678118654752f));
        }
        gsT[k][j] = v;
    }
    __syncthreads();

    int g  = tid >> 7;
    int d  = tid & 127;
    int jb = g * 16;

    int t0 = types_s[jb];
    bool uniform = true;
#pragma unroll
    for (int j = 1; j < 16; j++) uniform &= (types_s[jb + j] == t0);

    if (uniform) {
        const float* AwT = Aw + t0 * DD * DD;
        float bA = Ab[t0 * DD + d];
        unsigned long long aA[8];
#pragma unroll
        for (int p = 0; p < 8; p++) aA[p] = pack2(bA, bA);
#pragma unroll 4
        for (int k = 0; k < DD; k++) {
            float w = AwT[k * DD + d];
            unsigned long long w2 = pack2(w, w);
#pragma unroll
            for (int p = 0; p < 8; p++) {
                unsigned long long xp =
                    *(const unsigned long long*)&gsT[k][jb + 2 * p];
                fma2(aA[p], xp, w2);
            }
        }
        float sk = skip[t0];
        float alpha = 1.f / (1.f + __expf(-sk));
        float beta  = 1.f - alpha;
#pragma unroll
        for (int p = 0; p < 8; p++) {
            int j0 = jb + 2 * p;
            int n0 = nodes_s[j0], n1 = nodes_s[j0 + 1];
            float lo, hi;
            unpack2(aA[p], lo, hi);
            if (n0 >= 0) out[n0 * DD + d] = lo * alpha + x[n0 * DD + d] * beta;
            if (n1 >= 0) out[n1 * DD + d] = hi * alpha + x[n1 * DD + d] * beta;
        }
    } else {
        for (int j = 0; j < 16; j++) {
            int nd = nodes_s[jb + j];
            if (nd < 0) continue;
            int t = types_s[jb + j];
            float aA = Ab[t * DD + d];
            for (int k = 0; k < DD; k++)
                aA += gsT[k][jb + j] * Aw[(t * DD + k) * DD + d];
            float sk = skip[t];
            float alpha = 1.f / (1.f + __expf(-sk));
            out[nd * DD + d] = aA * alpha + x[nd * DD + d] * (1.f - alpha);
        }
    }
}

// --------------------------------- launcher -----------------------------------
extern "C" void kernel_launch(void* const* d_in, const int* in_sizes, int n_in,
                              void* d_out, int out_size) {
    const float* node_inp  = (const float*)d_in[0];
    const int*   node_type = (const int*)  d_in[1];
    const int*   edge_index= (const int*)  d_in[2];
    const int*   edge_type = (const int*)  d_in[3];
    const float* Kw = (const float*)d_in[5];
    const float* Kb = (const float*)d_in[6];
    const float* Qw = (const float*)d_in[7];
    const float* Qb = (const float*)d_in[8];
    const float* Vw = (const float*)d_in[9];
    const float* Vb = (const float*)d_in[10];
    const float* Aw = (const float*)d_in[11];
    const float* Ab = (const float*)d_in[12];
    const float* pri  = (const float*)d_in[13];
    const float* Ratt = (const float*)d_in[14];
    const float* Rmsg = (const float*)d_in[15];
    const float* s2u  = (const float*)d_in[16];
    const float* skip = (const float*)d_in[17];
    float* out = (float*)d_out;

    int n = in_sizes[1];
    int e = in_sizes[3];
    if (n > NMAX) n = NMAX;
    if (e > EMAX) e = EMAX;
    int n4 = n * RR;

    int nb  = (n + 255) / 256;
    int n4b = (n4 + 255) / 256;
    int eb  = (e + 255) / 256;
    int sb  = (n4 + 1023) / 1024;

    k_init<<<n4b + 65, 256>>>(Vw, Vb, s2u, n, n4b);
    k_nodehist<<<nb, 256>>>(node_type, n);
    k_nodescatter<<<nb, 256>>>(node_type, n);
    k_proj<<<(n + NPB - 1) / NPB, 256>>>(node_inp, node_type, Kw, Kb, Qw, Qb,
                                         Vw, Vb, Ratt, n);
    k_edgestats<<<eb, 256>>>(edge_index, edge_type, e);
    k_scan1<<<sb, 1024>>>(n4);
    k_scan2<<<1, 32>>>(sb, n4);
    k_scan3<<<n4b, 256>>>(n4);
    k_scatter_edges<<<eb, 256>>>(edge_index, edge_type, node_type, e);
    k_attn<<<(n + 7) / 8, 256>>>(node_type, pri, Rmsg, n);
    k_final<<<(n + NPB - 1) / NPB, 256>>>(node_inp, node_type, edge_index,
                                          Aw, Ab, skip, out, n, e);
}

// round 4
// speedup vs baseline: 1.0319x; 1.0319x over previous
#include <cuda_runtime.h>
#include <math.h>

#define NMAX 40000
#define EMAX 640000
#define DD   128
#define HH   8
#define DKK  16
#define TT   3
#define RR   4
#define NPP  16              // nodes per proj block
#define PPAD 18              // proj smem row stride
#define NPB  32              // nodes per final block
#define XPAD 34              // final smem row stride
#define N4   (NMAX * RR)

// ---------------- scratch (device globals) ------------------------------------
__device__ float g_k   [NMAX * DD];
__device__ float g_v   [NMAX * DD];
__device__ float g_qt  [NMAX * RR * DD];
__device__ float g_sp  [NMAX * DD];
__device__ float g_aggr[NMAX * DD];
__device__ float g_Wsp [DD * DD];
__device__ float g_bsp [DD];
__device__ int   g_win [NMAX];
__device__ int   g_thist[N4];
__device__ int   g_toff [N4 + 1];
__device__ int   g_tcur [N4];
__device__ int   g_epack[EMAX];
__device__ int   g_bsum [256];
__device__ int   g_typehist[TT];
__device__ int   g_typecur [TT];
__device__ int   g_perm [NMAX];

// ---------------- packed f32x2 helpers ----------------------------------------
__device__ __forceinline__ unsigned long long pack2(float a, float b) {
    unsigned long long r;
    asm("mov.b64 %0, {%1, %2};" : "=l"(r) : "f"(a), "f"(b));
    return r;
}
__device__ __forceinline__ void unpack2(unsigned long long v, float& lo, float& hi) {
    asm("mov.b64 {%0, %1}, %2;" : "=f"(lo), "=f"(hi) : "l"(v));
}
__device__ __forceinline__ void fma2(unsigned long long& acc,
                                     unsigned long long x, unsigned long long w) {
    asm("fma.rn.f32x2 %0, %1, %2, %0;" : "+l"(acc) : "l"(x), "l"(w));
}

// ------------------ init: zero hists + precompute Wsp = Vw[1]@s2u --------------
__global__ void k_init(const float* __restrict__ Vw, const float* __restrict__ Vb,
                       const float* __restrict__ s2u, int n, int zb) {
    if ((int)blockIdx.x < zb) {
        int i = blockIdx.x * 256 + threadIdx.x;
        if (i < n) g_win[i] = -1;
        if (i < 4 * n) g_thist[i] = 0;
        if (i < TT) { g_typehist[i] = 0; g_typecur[i] = 0; }
    } else {
        int bi  = blockIdx.x - zb;
        int row = bi * 2 + (threadIdx.x >> 7);
        int d   = threadIdx.x & 127;
        if (row < DD) {
            float acc = 0.f;
            for (int m = 0; m < DD; m++)
                acc += Vw[(DD + row) * DD + m] * s2u[m * DD + d];
            g_Wsp[row * DD + d] = acc;
        } else if (row == DD) {
            float acc = 0.f;
            for (int m = 0; m < DD; m++)
                acc += Vb[DD + m] * s2u[m * DD + d];
            g_bsp[d] = acc;
        }
    }
}

__global__ void k_nodehist(const int* __restrict__ ntype, int n) {
    int i = blockIdx.x * blockDim.x + threadIdx.x;
    if (i < n) atomicAdd(&g_typehist[ntype[i]], 1);
}

__global__ void k_nodescatter(const int* __restrict__ ntype, int n) {
    int i = blockIdx.x * blockDim.x + threadIdx.x;
    if (i >= n) return;
    int t = ntype[i];
    int off = 0;
    for (int ty = 0; ty < TT; ty++) if (ty < t) off += g_typehist[ty];
    int pos = off + atomicAdd(&g_typecur[t], 1);
    g_perm[pos] = i;
}

// ----- projections (K,Q,V,speaker) + per-relation Q transforms, f32x2 ---------
// 16 nodes/block, two groups of 8 (4 packed pairs) -> 32 accumulator regs.
__global__ void __launch_bounds__(256, 2)
k_proj(const float* __restrict__ x, const int* __restrict__ ntype,
       const float* __restrict__ Kw, const float* __restrict__ Kb,
       const float* __restrict__ Qw, const float* __restrict__ Qb,
       const float* __restrict__ Vw, const float* __restrict__ Vb,
       const float* __restrict__ Ratt, int n) {
    __shared__ __align__(16) float xsT[DD][PPAD];   // [feature][node]
    __shared__ __align__(16) float qsT[DD][PPAD];
    __shared__ int nodes_s[NPP], types_s[NPP];
    int tid  = threadIdx.x;
    int base = blockIdx.x * NPP;
    if (tid < NPP) {
        int idx = base + tid;
        int cidx = (idx < n) ? idx : (n - 1);
        nodes_s[tid] = (idx < n) ? g_perm[idx] : -1;
        types_s[tid] = ntype[g_perm[cidx]];
    }
    __syncthreads();
    // cooperative transposed load of x (NPP*DD = 2048 -> 8 iters)
    for (int idx = tid; idx < NPP * DD; idx += 256) {
        int j = idx >> 7;
        int k = idx & 127;
        int nd = nodes_s[j];
        xsT[k][j] = (nd >= 0) ? x[nd * DD + k] : 0.f;
    }
    __syncthreads();

    int g  = tid >> 7;      // group 0/1 -> 8 nodes each
    int d  = tid & 127;
    int jb = g * 8;

    int t0 = types_s[jb];
    bool uniform = true;
#pragma unroll
    for (int j = 1; j < 8; j++) uniform &= (types_s[jb + j] == t0);

    if (uniform) {
        const float* pK = Kw + t0 * DD * DD + d;
        const float* pQ = Qw + t0 * DD * DD + d;
        const float* pV = Vw + t0 * DD * DD + d;
        const float* pS = g_Wsp + d;
        float bK = Kb[t0 * DD + d], bQ = Qb[t0 * DD + d];
        float bV = Vb[t0 * DD + d], bS = g_bsp[d];
        unsigned long long aK[4], aQ[4], aV[4], aS[4];
#pragma unroll
        for (int p = 0; p < 4; p++) {
            aK[p] = pack2(bK, bK); aQ[p] = pack2(bQ, bQ);
            aV[p] = pack2(bV, bV); aS[p] = pack2(bS, bS);
        }
#pragma unroll 4
        for (int k = 0; k < DD; k++) {
            float fk = pK[k * DD];
            float fq = pQ[k * DD];
            float fv = pV[k * DD];
            float fs = pS[k * DD];
            unsigned long long wk = pack2(fk, fk);
            unsigned long long wq = pack2(fq, fq);
            unsigned long long wv = pack2(fv, fv);
            unsigned long long ws = pack2(fs, fs);
#pragma unroll
            for (int p = 0; p < 4; p++) {
                unsigned long long xp =
                    *(const unsigned long long*)&xsT[k][jb + 2 * p];
                fma2(aK[p], xp, wk);
                fma2(aQ[p], xp, wq);
                fma2(aV[p], xp, wv);
                fma2(aS[p], xp, ws);
            }
        }
#pragma unroll
        for (int p = 0; p < 4; p++) {
            int j0 = jb + 2 * p;
            int n0 = nodes_s[j0], n1 = nodes_s[j0 + 1];
            float lo, hi;
            unpack2(aK[p], lo, hi);
            if (n0 >= 0) g_k[n0 * DD + d] = lo;
            if (n1 >= 0) g_k[n1 * DD + d] = hi;
            unpack2(aV[p], lo, hi);
            if (n0 >= 0) g_v[n0 * DD + d] = lo;
            if (n1 >= 0) g_v[n1 * DD + d] = hi;
            unpack2(aS[p], lo, hi);
            if (n0 >= 0) g_sp[n0 * DD + d] = lo;
            if (n1 >= 0) g_sp[n1 * DD + d] = hi;
            unpack2(aQ[p], lo, hi);
            *(float2*)&qsT[d][j0] = make_float2(lo, hi);
        }
    } else {
        // rare boundary block: scalar per node
        for (int j = 0; j < 8; j++) {
            int nd = nodes_s[jb + j];
            int t  = types_s[jb + j];
            float aK = Kb[t * DD + d], aQ = Qb[t * DD + d];
            float aV = Vb[t * DD + d], aS = g_bsp[d];
            for (int k = 0; k < DD; k++) {
                float xv = xsT[k][jb + j];
                aK += xv * Kw[(t * DD + k) * DD + d];
                aQ += xv * Qw[(t * DD + k) * DD + d];
                aV += xv * Vw[(t * DD + k) * DD + d];
                aS += xv * g_Wsp[k * DD + d];
            }
            if (nd >= 0) {
                g_k [nd * DD + d] = aK;
                g_v [nd * DD + d] = aV;
                g_sp[nd * DD + d] = aS;
            }
            qsT[d][jb + j] = aQ;
        }
    }
    __syncthreads();

    // q' per relation: qt(h,dk) = sum_f q(h,f) * Ratt[r,h,dk,f]  (packed pairs)
    int h = d >> 4, dk = d & 15;
    for (int r = 0; r < RR; r++) {
        unsigned long long ar2[DKK];
#pragma unroll
        for (int f = 0; f < DKK; f++) {
            float a = Ratt[((r * HH + h) * DKK + dk) * DKK + f];
            ar2[f] = pack2(a, a);
        }
#pragma unroll
        for (int p = 0; p < 4; p++) {
            int j0 = jb + 2 * p;
            unsigned long long acc = pack2(0.f, 0.f);
#pragma unroll
            for (int f = 0; f < DKK; f++) {
                unsigned long long qp =
                    *(const unsigned long long*)&qsT[(h << 4) + f][j0];
                fma2(acc, qp, ar2[f]);
            }
            float lo, hi;
            unpack2(acc, lo, hi);
            int n0 = nodes_s[j0], n1 = nodes_s[j0 + 1];
            if (n0 >= 0) g_qt[(n0 * RR + r) * DD + d] = lo;
            if (n1 >= 0) g_qt[(n1 * RR + r) * DD + d] = hi;
        }
    }
}

// ------------------------------ edge setup ------------------------------------
__global__ void k_edgestats(const int* __restrict__ ei, const int* __restrict__ et, int e) {
    int i = blockIdx.x * blockDim.x + threadIdx.x;
    if (i >= e) return;
    int tgt = ei[e + i];
    int r   = et[i];
    atomicAdd(&g_thist[tgt * RR + r], 1);
    if (r == 0) atomicMax(&g_win[ei[i]], i);
}

__global__ void k_scan1(int n4) {
    __shared__ int buf[1024];
    int t = threadIdx.x;
    int gid = blockIdx.x * 1024 + t;
    int v = (gid < n4) ? g_thist[gid] : 0;
    buf[t] = v;
    __syncthreads();
    for (int off = 1; off < 1024; off <<= 1) {
        int x = (t >= off) ? buf[t - off] : 0;
        __syncthreads();
        buf[t] += x;
        __syncthreads();
    }
    if (gid < n4) g_toff[gid] = buf[t] - v;
    if (t == 1023) g_bsum[blockIdx.x] = buf[t];
}

__global__ void k_scan2(int nblocks, int n4) {
    if (threadIdx.x == 0) {
        int run = 0;
        for (int b = 0; b < nblocks; b++) { int x = g_bsum[b]; g_bsum[b] = run; run += x; }
        g_toff[n4] = run;
    }
}

__global__ void k_scan3(int n4) {
    int gid = blockIdx.x * blockDim.x + threadIdx.x;
    if (gid < n4) {
        int v = g_toff[gid] + g_bsum[gid >> 10];
        g_toff[gid] = v;
        g_tcur[gid] = v;
    }
}

__global__ void k_scatter_edges(const int* __restrict__ ei, const int* __restrict__ et,
                                const int* __restrict__ ntype, int e) {
    int i = blockIdx.x * blockDim.x + threadIdx.x;
    if (i >= e) return;
    int src = ei[i];
    int tgt = ei[e + i];
    int r   = et[i];
    int st  = ntype[src];
    int pos = atomicAdd(&g_tcur[tgt * RR + r], 1);
    g_epack[pos] = src | (st << 16);
}

// ------- attention: warp per target, per-relation sub-loops --------------------
__global__ void __launch_bounds__(256)
k_attn(const int* __restrict__ ntype, const float* __restrict__ pri,
       const float* __restrict__ Rmsg, int n) {
    __shared__ float accsh[8][RR][DD];
    int warp = threadIdx.x >> 5, lane = threadIdx.x & 31;
    int i = blockIdx.x * 8 + warp;
    if (i >= n) return;
    int d0 = lane * 4;
    int h  = lane >> 2;

    int tt = ntype[i];
    float p0[TT], p1[TT], p2[TT], p3[TT];
#pragma unroll
    for (int st = 0; st < TT; st++) {
        p0[st] = pri[((tt * RR + 0) * TT + st) * HH + h];
        p1[st] = pri[((tt * RR + 1) * TT + st) * HH + h];
        p2[st] = pri[((tt * RR + 2) * TT + st) * HH + h];
        p3[st] = pri[((tt * RR + 3) * TT + st) * HH + h];
    }

    float den = 0.f;
    float4 acc[RR];
#pragma unroll
    for (int r = 0; r < RR; r++) acc[r] = make_float4(0.f, 0.f, 0.f, 0.f);

#pragma unroll
    for (int r = 0; r < RR; r++) {
        int beg = g_toff[i * RR + r], end = g_toff[i * RR + r + 1];
        if (beg == end) continue;
        float4 qtr = *(const float4*)&g_qt[(i * RR + r) * DD + d0];
        float4 a = make_float4(0.f, 0.f, 0.f, 0.f);
        for (int idx = beg; idx < end; idx++) {
            int pk  = g_epack[idx];
            int src = pk & 0xFFFF;
            int st  = pk >> 16;
            const float4 k4 = *(const float4*)&g_k[src * DD + d0];
            float s = qtr.x * k4.x + qtr.y * k4.y + qtr.z * k4.z + qtr.w * k4.w;
            s += __shfl_xor_sync(0xffffffffu, s, 1);
            s += __shfl_xor_sync(0xffffffffu, s, 2);
            float pr = (r == 0) ? p0[0] : (r == 1) ? p1[0] : (r == 2) ? p2[0] : p3[0];
            if (st == 1) pr = (r == 0) ? p0[1] : (r == 1) ? p1[1] : (r == 2) ? p2[1] : p3[1];
            if (st == 2) pr = (r == 0) ? p0[2] : (r == 1) ? p1[2] : (r == 2) ? p2[2] : p3[2];
            float pe = __expf(s * pr * 0.25f);
            den += pe;
            const float4 v4 = *(const float4*)&g_v[src * DD + d0];
            a.x += pe * v4.x;
            a.y += pe * v4.y;
            a.z += pe * v4.z;
            a.w += pe * v4.w;
        }
        acc[r] = a;
    }

    float inv = 1.f / (den + 1e-16f);
#pragma unroll
    for (int r = 0; r < RR; r++) {
        accsh[warp][r][d0 + 0] = acc[r].x * inv;
        accsh[warp][r][d0 + 1] = acc[r].y * inv;
        accsh[warp][r][d0 + 2] = acc[r].z * inv;
        accsh[warp][r][d0 + 3] = acc[r].w * inv;
    }
    __syncwarp();

    int f0 = (lane & 3) * 4;
    float4 o = make_float4(0.f, 0.f, 0.f, 0.f);
#pragma unroll
    for (int r = 0; r < RR; r++) {
#pragma unroll 4
        for (int dk = 0; dk < DKK; dk++) {
            float a = accsh[warp][r][(h << 4) + dk];
            const float4 w = *(const float4*)&Rmsg[(((r * HH + h) * DKK + dk) * DKK) + f0];
            o.x += a * w.x;
            o.y += a * w.y;
            o.z += a * w.z;
            o.w += a * w.w;
        }
    }
    *(float4*)&g_aggr[i * DD + d0] = o;
}

// ------------- final: speaker add + GELU + per-type A projection + skip -------
__global__ void __launch_bounds__(256, 2)
k_final(const float* __restrict__ x, const int* __restrict__ ntype,
        const int* __restrict__ ei,
        const float* __restrict__ Aw, const float* __restrict__ Ab,
        const float* __restrict__ skip, float* __restrict__ out, int n, int e) {
    __shared__ __align__(16) float gsT[DD][XPAD];
    __shared__ int nodes_s[NPB], types_s[NPB], spsrc_s[NPB];
    int tid  = threadIdx.x;
    int base = blockIdx.x * NPB;
    if (tid < NPB) {
        int idx = base + tid;
        int cidx = (idx < n) ? idx : (n - 1);
        int nd = (idx < n) ? g_perm[idx] : -1;
        nodes_s[tid] = nd;
        types_s[tid] = ntype[g_perm[cidx]];
        int sps = -1;
        if (nd >= 0) {
            int we = g_win[nd];
            if (we >= 0) sps = ei[e + we];
        }
        spsrc_s[tid] = sps;
    }
    __syncthreads();

    for (int idx = tid; idx < NPB * DD; idx += 256) {
        int j = idx >> 7;
        int k = idx & 127;
        int nd = nodes_s[j];
        float v = 0.f;
        if (nd >= 0) {
            v = g_aggr[nd * DD + k];
            int sps = spsrc_s[j];
            if (sps >= 0) v += g_sp[sps * DD + k];
            v = 0.5f * v * (1.f + erff(v * 0.70710678118654752f));
        }
        gsT[k][j] = v;
    }
    __syncthreads();

    int g  = tid >> 7;
    int d  = tid & 127;
    int jb = g * 16;

    int t0 = types_s[jb];
    bool uniform = true;
#pragma unroll
    for (int j = 1; j < 16; j++) uniform &= (types_s[jb + j] == t0);

    if (uniform) {
        const float* pA = Aw + t0 * DD * DD + d;
        float bA = Ab[t0 * DD + d];
        unsigned long long aA[8];
#pragma unroll
        for (int p = 0; p < 8; p++) aA[p] = pack2(bA, bA);
#pragma unroll 4
        for (int k = 0; k < DD; k++) {
            float w = pA[k * DD];
            unsigned long long w2 = pack2(w, w);
#pragma unroll
            for (int p = 0; p < 8; p++) {
                unsigned long long xp =
                    *(const unsigned long long*)&gsT[k][jb + 2 * p];
                fma2(aA[p], xp, w2);
            }
        }
        float sk = skip[t0];
        float alpha = 1.f / (1.f + __expf(-sk));
        float beta  = 1.f - alpha;
#pragma unroll
        for (int p = 0; p < 8; p++) {
            int j0 = jb + 2 * p;
            int n0 = nodes_s[j0], n1 = nodes_s[j0 + 1];
            float lo, hi;
            unpack2(aA[p], lo, hi);
            if (n0 >= 0) out[n0 * DD + d] = lo * alpha + x[n0 * DD + d] * beta;
            if (n1 >= 0) out[n1 * DD + d] = hi * alpha + x[n1 * DD + d] * beta;
        }
    } else {
        for (int j = 0; j < 16; j++) {
            int nd = nodes_s[jb + j];
            if (nd < 0) continue;
            int t = types_s[jb + j];
            float aA = Ab[t * DD + d];
            for (int k = 0; k < DD; k++)
                aA += gsT[k][jb + j] * Aw[(t * DD + k) * DD + d];
            float sk = skip[t];
            float alpha = 1.f / (1.f + __expf(-sk));
            out[nd * DD + d] = aA * alpha + x[nd * DD + d] * (1.f - alpha);
        }
    }
}

// --------------------------------- launcher -----------------------------------
extern "C" void kernel_launch(void* const* d_in, const int* in_sizes, int n_in,
                              void* d_out, int out_size) {
    const float* node_inp  = (const float*)d_in[0];
    const int*   node_type = (const int*)  d_in[1];
    const int*   edge_index= (const int*)  d_in[2];
    const int*   edge_type = (const int*)  d_in[3];
    const float* Kw = (const float*)d_in[5];
    const float* Kb = (const float*)d_in[6];
    const float* Qw = (const float*)d_in[7];
    const float* Qb = (const float*)d_in[8];
    const float* Vw = (const float*)d_in[9];
    const float* Vb = (const float*)d_in[10];
    const float* Aw = (const float*)d_in[11];
    const float* Ab = (const float*)d_in[12];
    const float* pri  = (const float*)d_in[13];
    const float* Ratt = (const float*)d_in[14];
    const float* Rmsg = (const float*)d_in[15];
    const float* s2u  = (const float*)d_in[16];
    const float* skip = (const float*)d_in[17];
    float* out = (float*)d_out;

    int n = in_sizes[1];
    int e = in_sizes[3];
    if (n > NMAX) n = NMAX;
    if (e > EMAX) e = EMAX;
    int n4 = n * RR;

    int nb  = (n + 255) / 256;
    int n4b = (n4 + 255) / 256;
    int eb  = (e + 255) / 256;
    int sb  = (n4 + 1023) / 1024;

    k_init<<<n4b + 65, 256>>>(Vw, Vb, s2u, n, n4b);
    k_nodehist<<<nb, 256>>>(node_type, n);
    k_nodescatter<<<nb, 256>>>(node_type, n);
    k_proj<<<(n + NPP - 1) / NPP, 256>>>(node_inp, node_type, Kw, Kb, Qw, Qb,
                                         Vw, Vb, Ratt, n);
    k_edgestats<<<eb, 256>>>(edge_index, edge_type, e);
    k_scan1<<<sb, 1024>>>(n4);
    k_scan2<<<1, 32>>>(sb, n4);
    k_scan3<<<n4b, 256>>>(n4);
    k_scatter_edges<<<eb, 256>>>(edge_index, edge_type, node_type, e);
    k_attn<<<(n + 7) / 8, 256>>>(node_type, pri, Rmsg, n);
    k_final<<<(n + NPB - 1) / NPB, 256>>>(node_inp, node_type, edge_index,
                                          Aw, Ab, skip, out, n, e);
}

// round 5
// speedup vs baseline: 1.0631x; 1.0303x over previous
#include <cuda_runtime.h>
#include <math.h>

#define NMAX 40000
#define EMAX 640000
#define DD   128
#define HH   8
#define DKK  16
#define TT   3
#define RR   4
#define NPP  16              // nodes per proj block
#define PPAD 18              // proj smem row stride (even for float2, odd-ish banks)
#define KT   8               // k-tile rows staged per cp.async stage
#define NT   (DD / KT)       // 16 tiles
#define NPB  32              // nodes per final block
#define XPAD 34              // final smem row stride
#define N4   (NMAX * RR)

// ---------------- scratch (device globals) ------------------------------------
__device__ float g_k   [NMAX * DD];
__device__ float g_v   [NMAX * DD];
__device__ float g_qt  [NMAX * RR * DD];
__device__ float g_sp  [NMAX * DD];
__device__ float g_aggr[NMAX * DD];
__device__ float g_Wsp [DD * DD];
__device__ float g_bsp [DD];
__device__ int   g_win [NMAX];
__device__ int   g_thist[N4];
__device__ int   g_toff [N4 + 1];
__device__ int   g_tcur [N4];
__device__ int   g_epack[EMAX];
__device__ int   g_bsum [256];
__device__ int   g_typehist[TT];
__device__ int   g_typecur [TT];
__device__ int   g_perm [NMAX];

// ---------------- packed f32x2 helpers ----------------------------------------
__device__ __forceinline__ unsigned long long pack2(float a, float b) {
    unsigned long long r;
    asm("mov.b64 %0, {%1, %2};" : "=l"(r) : "f"(a), "f"(b));
    return r;
}
__device__ __forceinline__ void unpack2(unsigned long long v, float& lo, float& hi) {
    asm("mov.b64 {%0, %1}, %2;" : "=f"(lo), "=f"(hi) : "l"(v));
}
__device__ __forceinline__ void fma2(unsigned long long& acc,
                                     unsigned long long x, unsigned long long w) {
    asm("fma.rn.f32x2 %0, %1, %2, %0;" : "+l"(acc) : "l"(x), "l"(w));
}

// ------------------ init: zero hists + precompute Wsp = Vw[1]@s2u --------------
__global__ void k_init(const float* __restrict__ Vw, const float* __restrict__ Vb,
                       const float* __restrict__ s2u, int n, int zb) {
    if ((int)blockIdx.x < zb) {
        int i = blockIdx.x * 256 + threadIdx.x;
        if (i < n) g_win[i] = -1;
        if (i < 4 * n) g_thist[i] = 0;
        if (i < TT) { g_typehist[i] = 0; g_typecur[i] = 0; }
    } else {
        int bi  = blockIdx.x - zb;
        int row = bi * 2 + (threadIdx.x >> 7);
        int d   = threadIdx.x & 127;
        if (row < DD) {
            float acc = 0.f;
            for (int m = 0; m < DD; m++)
                acc += Vw[(DD + row) * DD + m] * s2u[m * DD + d];
            g_Wsp[row * DD + d] = acc;
        } else if (row == DD) {
            float acc = 0.f;
            for (int m = 0; m < DD; m++)
                acc += Vb[DD + m] * s2u[m * DD + d];
            g_bsp[d] = acc;
        }
    }
}

__global__ void k_nodehist(const int* __restrict__ ntype, int n) {
    int i = blockIdx.x * blockDim.x + threadIdx.x;
    if (i < n) atomicAdd(&g_typehist[ntype[i]], 1);
}

__global__ void k_nodescatter(const int* __restrict__ ntype, int n) {
    int i = blockIdx.x * blockDim.x + threadIdx.x;
    if (i >= n) return;
    int t = ntype[i];
    int off = 0;
    for (int ty = 0; ty < TT; ty++) if (ty < t) off += g_typehist[ty];
    int pos = off + atomicAdd(&g_typecur[t], 1);
    g_perm[pos] = i;
}

// ----- projections (K,Q,V,speaker) + per-relation Q transforms ----------------
// Weights for K/Q/V staged through smem via cp.async double buffering.
__global__ void __launch_bounds__(256, 2)
k_proj(const float* __restrict__ x, const int* __restrict__ ntype,
       const float* __restrict__ Kw, const float* __restrict__ Kb,
       const float* __restrict__ Qw, const float* __restrict__ Qb,
       const float* __restrict__ Vw, const float* __restrict__ Vb,
       const float* __restrict__ Ratt, int n) {
    __shared__ __align__(16) float xsT[DD][PPAD];          // x transposed; reused as qsT
    __shared__ __align__(16) float wbuf[2][3][KT][DD];     // 24.5 KB staged weights
    __shared__ int nodes_s[NPP], types_s[NPP];
    int tid  = threadIdx.x;
    int base = blockIdx.x * NPP;
    if (tid < NPP) {
        int idx = base + tid;
        int cidx = (idx < n) ? idx : (n - 1);
        nodes_s[tid] = (idx < n) ? g_perm[idx] : -1;
        types_s[tid] = ntype[g_perm[cidx]];
    }
    __syncthreads();
    for (int idx = tid; idx < NPP * DD; idx += 256) {
        int j = idx >> 7;
        int k = idx & 127;
        int nd = nodes_s[j];
        xsT[k][j] = (nd >= 0) ? x[nd * DD + k] : 0.f;
    }

    int g  = tid >> 7;      // group 0/1 -> 8 nodes each
    int d  = tid & 127;
    int jb = g * 8;

    int t0b = types_s[0];
    bool blk_uniform = true;
#pragma unroll
    for (int j = 1; j < NPP; j++) blk_uniform &= (types_s[j] == t0b);
    __syncthreads();

    if (blk_uniform) {
        const float* WK = Kw + t0b * DD * DD;
        const float* WQ = Qw + t0b * DD * DD;
        const float* WV = Vw + t0b * DD * DD;
        // staging lambda-ish: each thread copies 3x 16B per stage
        int s_mat[3], s_kk[3], s_d4[3];
#pragma unroll
        for (int t = 0; t < 3; t++) {
            s_mat[t] = t;                 // fi = t*256 + tid, fi>>8 == t
            int rem = tid;                // fi & 255 == tid
            s_kk[t] = rem >> 5;
            s_d4[t] = rem & 31;
        }
        // NOTE: above mapping ignores rem>255 case; tid<256 so rem==tid, kk=tid>>5 (0..7), d4=tid&31. ok.
        const float* srcs[3] = {WK, WQ, WV};

        // prologue: stage tile 0 into buf 0
#pragma unroll
        for (int t = 0; t < 3; t++) {
            const float* src = srcs[t] + (0 * KT + s_kk[t]) * DD + s_d4[t] * 4;
            unsigned int da = (unsigned int)__cvta_generic_to_shared(
                &wbuf[0][t][s_kk[t]][s_d4[t] * 4]);
            asm volatile("cp.async.cg.shared.global [%0], [%1], 16;"
                         :: "r"(da), "l"(src) : "memory");
        }
        asm volatile("cp.async.commit_group;" ::: "memory");

        float bK = Kb[t0b * DD + d], bQ = Qb[t0b * DD + d];
        float bV = Vb[t0b * DD + d], bS = g_bsp[d];
        const float* pS = g_Wsp + d;
        unsigned long long aK[4], aQ[4], aV[4], aS[4];
#pragma unroll
        for (int p = 0; p < 4; p++) {
            aK[p] = pack2(bK, bK); aQ[p] = pack2(bQ, bQ);
            aV[p] = pack2(bV, bV); aS[p] = pack2(bS, bS);
        }

        for (int tile = 0; tile < NT; tile++) {
            if (tile + 1 < NT) {
                int stg = (tile + 1) & 1;
#pragma unroll
                for (int t = 0; t < 3; t++) {
                    const float* src = srcs[t] + ((tile + 1) * KT + s_kk[t]) * DD + s_d4[t] * 4;
                    unsigned int da = (unsigned int)__cvta_generic_to_shared(
                        &wbuf[stg][t][s_kk[t]][s_d4[t] * 4]);
                    asm volatile("cp.async.cg.shared.global [%0], [%1], 16;"
                                 :: "r"(da), "l"(src) : "memory");
                }
                asm volatile("cp.async.commit_group;" ::: "memory");
                asm volatile("cp.async.wait_group 1;" ::: "memory");
            } else {
                asm volatile("cp.async.wait_group 0;" ::: "memory");
            }
            __syncthreads();
            int cur = tile & 1;
#pragma unroll
            for (int kk = 0; kk < KT; kk++) {
                int k = tile * KT + kk;
                float fk = wbuf[cur][0][kk][d];
                float fq = wbuf[cur][1][kk][d];
                float fv = wbuf[cur][2][kk][d];
                float fs = pS[k * DD];
                unsigned long long wk = pack2(fk, fk);
                unsigned long long wq = pack2(fq, fq);
                unsigned long long wv = pack2(fv, fv);
                unsigned long long ws = pack2(fs, fs);
#pragma unroll
                for (int p = 0; p < 4; p++) {
                    unsigned long long xp =
                        *(const unsigned long long*)&xsT[k][jb + 2 * p];
                    fma2(aK[p], xp, wk);
                    fma2(aQ[p], xp, wq);
                    fma2(aV[p], xp, wv);
                    fma2(aS[p], xp, ws);
                }
            }
            __syncthreads();
        }

#pragma unroll
        for (int p = 0; p < 4; p++) {
            int j0 = jb + 2 * p;
            int n0 = nodes_s[j0], n1 = nodes_s[j0 + 1];
            float lo, hi;
            unpack2(aK[p], lo, hi);
            if (n0 >= 0) g_k[n0 * DD + d] = lo;
            if (n1 >= 0) g_k[n1 * DD + d] = hi;
            unpack2(aV[p], lo, hi);
            if (n0 >= 0) g_v[n0 * DD + d] = lo;
            if (n1 >= 0) g_v[n1 * DD + d] = hi;
            unpack2(aS[p], lo, hi);
            if (n0 >= 0) g_sp[n0 * DD + d] = lo;
            if (n1 >= 0) g_sp[n1 * DD + d] = hi;
        }
        __syncthreads();   // all xsT reads done; reuse xsT as qsT
#pragma unroll
        for (int p = 0; p < 4; p++) {
            int j0 = jb + 2 * p;
            float lo, hi;
            unpack2(aQ[p], lo, hi);
            *(float2*)&xsT[d][j0] = make_float2(lo, hi);
        }
    } else {
        // rare mixed-type block: direct-LDG scalar path
        float aK[8], aQ[8], aV[8], aS[8];
#pragma unroll
        for (int j = 0; j < 8; j++) {
            int t = types_s[jb + j];
            aK[j] = Kb[t * DD + d];
            aQ[j] = Qb[t * DD + d];
            aV[j] = Vb[t * DD + d];
            aS[j] = g_bsp[d];
        }
        for (int k = 0; k < DD; k++) {
            float ws = g_Wsp[k * DD + d];
#pragma unroll
            for (int j = 0; j < 8; j++) {
                int t = types_s[jb + j];
                float xv = xsT[k][jb + j];
                aK[j] += xv * Kw[(t * DD + k) * DD + d];
                aQ[j] += xv * Qw[(t * DD + k) * DD + d];
                aV[j] += xv * Vw[(t * DD + k) * DD + d];
                aS[j] += xv * ws;
            }
        }
#pragma unroll
        for (int j = 0; j < 8; j++) {
            int nd = nodes_s[jb + j];
            if (nd >= 0) {
                g_k [nd * DD + d] = aK[j];
                g_v [nd * DD + d] = aV[j];
                g_sp[nd * DD + d] = aS[j];
            }
        }
        __syncthreads();
#pragma unroll
        for (int j = 0; j < 8; j++) xsT[d][jb + j] = aQ[j];
    }
    __syncthreads();

    // q' per relation: qt(h,dk) = sum_f q(h,f) * Ratt[r,h,dk,f]  (q in xsT[d][j])
    int h = d >> 4, dk = d & 15;
    for (int r = 0; r < RR; r++) {
        unsigned long long ar2[DKK];
#pragma unroll
        for (int f = 0; f < DKK; f++) {
            float a = Ratt[((r * HH + h) * DKK + dk) * DKK + f];
            ar2[f] = pack2(a, a);
        }
#pragma unroll
        for (int p = 0; p < 4; p++) {
            int j0 = jb + 2 * p;
            unsigned long long acc = pack2(0.f, 0.f);
#pragma unroll
            for (int f = 0; f < DKK; f++) {
                unsigned long long qp =
                    *(const unsigned long long*)&xsT[(h << 4) + f][j0];
                fma2(acc, qp, ar2[f]);
            }
            float lo, hi;
            unpack2(acc, lo, hi);
            int n0 = nodes_s[j0], n1 = nodes_s[j0 + 1];
            if (n0 >= 0) g_qt[(n0 * RR + r) * DD + d] = lo;
            if (n1 >= 0) g_qt[(n1 * RR + r) * DD + d] = hi;
        }
    }
}

// ------------------------------ edge setup ------------------------------------
__global__ void k_edgestats(const int* __restrict__ ei, const int* __restrict__ et, int e) {
    int i = blockIdx.x * blockDim.x + threadIdx.x;
    if (i >= e) return;
    int tgt = ei[e + i];
    int r   = et[i];
    atomicAdd(&g_thist[tgt * RR + r], 1);
    if (r == 0) atomicMax(&g_win[ei[i]], i);
}

__global__ void k_scan1(int n4) {
    __shared__ int buf[1024];
    int t = threadIdx.x;
    int gid = blockIdx.x * 1024 + t;
    int v = (gid < n4) ? g_thist[gid] : 0;
    buf[t] = v;
    __syncthreads();
    for (int off = 1; off < 1024; off <<= 1) {
        int x = (t >= off) ? buf[t - off] : 0;
        __syncthreads();
        buf[t] += x;
        __syncthreads();
    }
    if (gid < n4) g_toff[gid] = buf[t] - v;
    if (t == 1023) g_bsum[blockIdx.x] = buf[t];
}

__global__ void k_scan2(int nblocks, int n4) {
    if (threadIdx.x == 0) {
        int run = 0;
        for (int b = 0; b < nblocks; b++) { int x = g_bsum[b]; g_bsum[b] = run; run += x; }
        g_toff[n4] = run;
    }
}

__global__ void k_scan3(int n4) {
    int gid = blockIdx.x * blockDim.x + threadIdx.x;
    if (gid < n4) {
        int v = g_toff[gid] + g_bsum[gid >> 10];
        g_toff[gid] = v;
        g_tcur[gid] = v;
    }
}

__global__ void k_scatter_edges(const int* __restrict__ ei, const int* __restrict__ et,
                                const int* __restrict__ ntype, int e) {
    int i = blockIdx.x * blockDim.x + threadIdx.x;
    if (i >= e) return;
    int src = ei[i];
    int tgt = ei[e + i];
    int r   = et[i];
    int st  = ntype[src];
    int pos = atomicAdd(&g_tcur[tgt * RR + r], 1);
    g_epack[pos] = src | (st << 16);
}

// ------- attention: warp per target, per-relation sub-loops --------------------
__global__ void __launch_bounds__(256)
k_attn(const int* __restrict__ ntype, const float* __restrict__ pri,
       const float* __restrict__ Rmsg, int n) {
    __shared__ float accsh[8][RR][DD];
    int warp = threadIdx.x >> 5, lane = threadIdx.x & 31;
    int i = blockIdx.x * 8 + warp;
    if (i >= n) return;
    int d0 = lane * 4;
    int h  = lane >> 2;

    int tt = ntype[i];
    float p0[TT], p1[TT], p2[TT], p3[TT];
#pragma unroll
    for (int st = 0; st < TT; st++) {
        p0[st] = pri[((tt * RR + 0) * TT + st) * HH + h];
        p1[st] = pri[((tt * RR + 1) * TT + st) * HH + h];
        p2[st] = pri[((tt * RR + 2) * TT + st) * HH + h];
        p3[st] = pri[((tt * RR + 3) * TT + st) * HH + h];
    }

    float den = 0.f;
    float4 acc[RR];
#pragma unroll
    for (int r = 0; r < RR; r++) acc[r] = make_float4(0.f, 0.f, 0.f, 0.f);

#pragma unroll
    for (int r = 0; r < RR; r++) {
        int beg = g_toff[i * RR + r], end = g_toff[i * RR + r + 1];
        if (beg == end) continue;
        float4 qtr = *(const float4*)&g_qt[(i * RR + r) * DD + d0];
        float4 a = make_float4(0.f, 0.f, 0.f, 0.f);
        for (int idx = beg; idx < end; idx++) {
            int pk  = g_epack[idx];
            int src = pk & 0xFFFF;
            int st  = pk >> 16;
            const float4 k4 = *(const float4*)&g_k[src * DD + d0];
            float s = qtr.x * k4.x + qtr.y * k4.y + qtr.z * k4.z + qtr.w * k4.w;
            s += __shfl_xor_sync(0xffffffffu, s, 1);
            s += __shfl_xor_sync(0xffffffffu, s, 2);
            float pr = (r == 0) ? p0[0] : (r == 1) ? p1[0] : (r == 2) ? p2[0] : p3[0];
            if (st == 1) pr = (r == 0) ? p0[1] : (r == 1) ? p1[1] : (r == 2) ? p2[1] : p3[1];
            if (st == 2) pr = (r == 0) ? p0[2] : (r == 1) ? p1[2] : (r == 2) ? p2[2] : p3[2];
            float pe = __expf(s * pr * 0.25f);
            den += pe;
            const float4 v4 = *(const float4*)&g_v[src * DD + d0];
            a.x += pe * v4.x;
            a.y += pe * v4.y;
            a.z += pe * v4.z;
            a.w += pe * v4.w;
        }
        acc[r] = a;
    }

    float inv = 1.f / (den + 1e-16f);
#pragma unroll
    for (int r = 0; r < RR; r++) {
        accsh[warp][r][d0 + 0] = acc[r].x * inv;
        accsh[warp][r][d0 + 1] = acc[r].y * inv;
        accsh[warp][r][d0 + 2] = acc[r].z * inv;
        accsh[warp][r][d0 + 3] = acc[r].w * inv;
    }
    __syncwarp();

    int f0 = (lane & 3) * 4;
    float4 o = make_float4(0.f, 0.f, 0.f, 0.f);
#pragma unroll
    for (int r = 0; r < RR; r++) {
#pragma unroll 4
        for (int dk = 0; dk < DKK; dk++) {
            float a = accsh[warp][r][(h << 4) + dk];
            const float4 w = *(const float4*)&Rmsg[(((r * HH + h) * DKK + dk) * DKK) + f0];
            o.x += a * w.x;
            o.y += a * w.y;
            o.z += a * w.z;
            o.w += a * w.w;
        }
    }
    *(float4*)&g_aggr[i * DD + d0] = o;
}

// ------------- final: speaker add + GELU + per-type A projection + skip -------
__global__ void __launch_bounds__(256, 2)
k_final(const float* __restrict__ x, const int* __restrict__ ntype,
        const int* __restrict__ ei,
        const float* __restrict__ Aw, const float* __restrict__ Ab,
        const float* __restrict__ skip, float* __restrict__ out, int n, int e) {
    __shared__ __align__(16) float gsT[DD][XPAD];
    __shared__ int nodes_s[NPB], types_s[NPB], spsrc_s[NPB];
    int tid  = threadIdx.x;
    int base = blockIdx.x * NPB;
    if (tid < NPB) {
        int idx = base + tid;
        int cidx = (idx < n) ? idx : (n - 1);
        int nd = (idx < n) ? g_perm[idx] : -1;
        nodes_s[tid] = nd;
        types_s[tid] = ntype[g_perm[cidx]];
        int sps = -1;
        if (nd >= 0) {
            int we = g_win[nd];
            if (we >= 0) sps = ei[e + we];
        }
        spsrc_s[tid] = sps;
    }
    __syncthreads();

    for (int idx = tid; idx < NPB * DD; idx += 256) {
        int j = idx >> 7;
        int k = idx & 127;
        int nd = nodes_s[j];
        float v = 0.f;
        if (nd >= 0) {
            v = g_aggr[nd * DD + k];
            int sps = spsrc_s[j];
            if (sps >= 0) v += g_sp[sps * DD + k];
            v = 0.5f * v * (1.f + erff(v * 0.70710678118654752f));
        }
        gsT[k][j] = v;
    }
    __syncthreads();

    int g  = tid >> 7;
    int d  = tid & 127;
    int jb = g * 16;

    int t0 = types_s[jb];
    bool uniform = true;
#pragma unroll
    for (int j = 1; j < 16; j++) uniform &= (types_s[jb + j] == t0);

    if (uniform) {
        const float* pA = Aw + t0 * DD * DD + d;
        float bA = Ab[t0 * DD + d];
        unsigned long long aA[8];
#pragma unroll
        for (int p = 0; p < 8; p++) aA[p] = pack2(bA, bA);
#pragma unroll 4
        for (int k = 0; k < DD; k++) {
            float w = pA[k * DD];
            unsigned long long w2 = pack2(w, w);
#pragma unroll
            for (int p = 0; p < 8; p++) {
                unsigned long long xp =
                    *(const unsigned long long*)&gsT[k][jb + 2 * p];
                fma2(aA[p], xp, w2);
            }
        }
        float sk = skip[t0];
        float alpha = 1.f / (1.f + __expf(-sk));
        float beta  = 1.f - alpha;
#pragma unroll
        for (int p = 0; p < 8; p++) {
            int j0 = jb + 2 * p;
            int n0 = nodes_s[j0], n1 = nodes_s[j0 + 1];
            float lo, hi;
            unpack2(aA[p], lo, hi);
            if (n0 >= 0) out[n0 * DD + d] = lo * alpha + x[n0 * DD + d] * beta;
            if (n1 >= 0) out[n1 * DD + d] = hi * alpha + x[n1 * DD + d] * beta;
        }
    } else {
        for (int j = 0; j < 16; j++) {
            int nd = nodes_s[jb + j];
            if (nd < 0) continue;
            int t = types_s[jb + j];
            float aA = Ab[t * DD + d];
            for (int k = 0; k < DD; k++)
                aA += gsT[k][jb + j] * Aw[(t * DD + k) * DD + d];
            float sk = skip[t];
            float alpha = 1.f / (1.f + __expf(-sk));
            out[nd * DD + d] = aA * alpha + x[nd * DD + d] * (1.f - alpha);
        }
    }
}

// --------------------------------- launcher -----------------------------------
extern "C" void kernel_launch(void* const* d_in, const int* in_sizes, int n_in,
                              void* d_out, int out_size) {
    const float* node_inp  = (const float*)d_in[0];
    const int*   node_type = (const int*)  d_in[1];
    const int*   edge_index= (const int*)  d_in[2];
    const int*   edge_type = (const int*)  d_in[3];
    const float* Kw = (const float*)d_in[5];
    const float* Kb = (const float*)d_in[6];
    const float* Qw = (const float*)d_in[7];
    const float* Qb = (const float*)d_in[8];
    const float* Vw = (const float*)d_in[9];
    const float* Vb = (const float*)d_in[10];
    const float* Aw = (const float*)d_in[11];
    const float* Ab = (const float*)d_in[12];
    const float* pri  = (const float*)d_in[13];
    const float* Ratt = (const float*)d_in[14];
    const float* Rmsg = (const float*)d_in[15];
    const float* s2u  = (const float*)d_in[16];
    const float* skip = (const float*)d_in[17];
    float* out = (float*)d_out;

    int n = in_sizes[1];
    int e = in_sizes[3];
    if (n > NMAX) n = NMAX;
    if (e > EMAX) e = EMAX;
    int n4 = n * RR;

    int nb  = (n + 255) / 256;
    int n4b = (n4 + 255) / 256;
    int eb  = (e + 255) / 256;
    int sb  = (n4 + 1023) / 1024;

    k_init<<<n4b + 65, 256>>>(Vw, Vb, s2u, n, n4b);
    k_nodehist<<<nb, 256>>>(node_type, n);
    k_nodescatter<<<nb, 256>>>(node_type, n);
    k_proj<<<(n + NPP - 1) / NPP, 256>>>(node_inp, node_type, Kw, Kb, Qw, Qb,
                                         Vw, Vb, Ratt, n);
    k_edgestats<<<eb, 256>>>(edge_index, edge_type, e);
    k_scan1<<<sb, 1024>>>(n4);
    k_scan2<<<1, 32>>>(sb, n4);
    k_scan3<<<n4b, 256>>>(n4);
    k_scatter_edges<<<eb, 256>>>(edge_index, edge_type, node_type, e);
    k_attn<<<(n + 7) / 8, 256>>>(node_type, pri, Rmsg, n);
    k_final<<<(n + NPB - 1) / NPB, 256>>>(node_inp, node_type, edge_index,
                                          Aw, Ab, skip, out, n, e);
}

// round 6
// speedup vs baseline: 1.1377x; 1.0701x over previous
#include <cuda_runtime.h>
#include <math.h>

#define NMAX 40000
#define EMAX 640000
#define DD   128
#define HH   8
#define DKK  16
#define TT   3
#define RR   4
#define NPP  16              // nodes per proj block
#define XST  20              // xsN row stride (floats, mult of 4)
#define KT   8               // k rows per cp.async stage
#define NT   (DD / KT)
#define NPB  32              // nodes per final block
#define GST  36              // gsN row stride (floats, mult of 4)
#define N4   (NMAX * RR)

// ---------------- scratch (device globals) ------------------------------------
__device__ float g_k   [NMAX * DD];
__device__ float g_v   [NMAX * DD];
__device__ float g_qt  [NMAX * RR * DD];
__device__ float g_sp  [NMAX * DD];
__device__ float g_aggr[NMAX * DD];
__device__ float g_Wsp [DD * DD];
__device__ float g_bsp [DD];
__device__ unsigned long long g_Rp[RR * HH * 8 * DKK];  // packed Ratt d-pairs
__device__ int   g_win [NMAX];
__device__ int   g_thist[N4];
__device__ int   g_toff [N4 + 1];
__device__ int   g_tcur [N4];
__device__ int   g_epack[EMAX];
__device__ int   g_bsum [256];
__device__ int   g_typehist[TT];
__device__ int   g_typecur [TT];
__device__ int   g_perm [NMAX];

// ---------------- packed f32x2 helpers ----------------------------------------
__device__ __forceinline__ unsigned long long pack2(float a, float b) {
    unsigned long long r;
    asm("mov.b64 %0, {%1, %2};" : "=l"(r) : "f"(a), "f"(b));
    return r;
}
__device__ __forceinline__ void unpack2(unsigned long long v, float& lo, float& hi) {
    asm("mov.b64 {%0, %1}, %2;" : "=f"(lo), "=f"(hi) : "l"(v));
}
__device__ __forceinline__ void fma2(unsigned long long& acc,
                                     unsigned long long x, unsigned long long w) {
    asm("fma.rn.f32x2 %0, %1, %2, %0;" : "+l"(acc) : "l"(x), "l"(w));
}

// ------------------ init: zero hists + Wsp + packed Ratt ----------------------
__global__ void k_init(const float* __restrict__ Vw, const float* __restrict__ Vb,
                       const float* __restrict__ s2u, const float* __restrict__ Ratt,
                       int n, int zb) {
    int b = blockIdx.x;
    if (b < zb) {
        int i = b * 256 + threadIdx.x;
        if (i < n) g_win[i] = -1;
        if (i < 4 * n) g_thist[i] = 0;
        if (i < TT) { g_typehist[i] = 0; g_typecur[i] = 0; }
    } else if (b < zb + 65) {
        int bi  = b - zb;
        int row = bi * 2 + (threadIdx.x >> 7);
        int d   = threadIdx.x & 127;
        if (row < DD) {
            float acc = 0.f;
            for (int m = 0; m < DD; m++)
                acc += Vw[(DD + row) * DD + m] * s2u[m * DD + d];
            g_Wsp[row * DD + d] = acc;
        } else if (row == DD) {
            float acc = 0.f;
            for (int m = 0; m < DD; m++)
                acc += Vb[DD + m] * s2u[m * DD + d];
            g_bsp[d] = acc;
        }
    } else {
        int idx = (b - zb - 65) * 256 + threadIdx.x;   // 0..4095
        if (idx < RR * HH * 8 * DKK) {
            int f   = idx & 15;
            int dkp = (idx >> 4) & 7;
            int h   = (idx >> 7) & 7;
            int r   = idx >> 10;
            float a0 = Ratt[((r * HH + h) * DKK + 2 * dkp)     * DKK + f];
            float a1 = Ratt[((r * HH + h) * DKK + 2 * dkp + 1) * DKK + f];
            g_Rp[idx] = pack2(a0, a1);
        }
    }
}

__global__ void k_nodehist(const int* __restrict__ ntype, int n) {
    int i = blockIdx.x * blockDim.x + threadIdx.x;
    if (i < n) atomicAdd(&g_typehist[ntype[i]], 1);
}

__global__ void k_nodescatter(const int* __restrict__ ntype, int n) {
    int i = blockIdx.x * blockDim.x + threadIdx.x;
    if (i >= n) return;
    int t = ntype[i];
    int off = 0;
    for (int ty = 0; ty < TT; ty++) if (ty < t) off += g_typehist[ty];
    int pos = off + atomicAdd(&g_typecur[t], 1);
    g_perm[pos] = i;
}

// ----- projections (K,Q,V,speaker) + per-relation Q transforms ----------------
// d-pair layout: thread owns 2 output columns; 4 groups x 4 nodes = 16 nodes.
__global__ void __launch_bounds__(256, 3)
k_proj(const float* __restrict__ x, const int* __restrict__ ntype,
       const float* __restrict__ Kw, const float* __restrict__ Kb,
       const float* __restrict__ Qw, const float* __restrict__ Qb,
       const float* __restrict__ Vw, const float* __restrict__ Vb,
       int n) {
    __shared__ __align__(16) float xsN[DD][XST];        // x (then reused for q)
    __shared__ __align__(16) float wbuf[2][3][KT][DD];  // staged K/Q/V weights
    __shared__ int nodes_s[NPP], types_s[NPP];
    int tid  = threadIdx.x;
    int base = blockIdx.x * NPP;
    if (tid < NPP) {
        int idx = base + tid;
        int cidx = (idx < n) ? idx : (n - 1);
        nodes_s[tid] = (idx < n) ? g_perm[idx] : -1;
        types_s[tid] = ntype[g_perm[cidx]];
    }
    __syncthreads();
    for (int idx = tid; idx < NPP * DD; idx += 256) {
        int j = idx >> 7;
        int k = idx & 127;
        int nd = nodes_s[j];
        xsN[k][j] = (nd >= 0) ? x[nd * DD + k] : 0.f;
    }

    int g  = tid >> 6;       // 4 groups of 64 threads
    int p  = tid & 63;
    int d0 = 2 * p;
    int jb = g * 4;

    int t0 = types_s[0];
    bool uniform = true;
#pragma unroll
    for (int j = 1; j < NPP; j++) uniform &= (types_s[j] == t0);
    __syncthreads();

    if (uniform) {
        const float* srcs[3] = {Kw + t0 * DD * DD, Qw + t0 * DD * DD, Vw + t0 * DD * DD};
        int s_kk = tid >> 5, s_d4 = tid & 31;
#pragma unroll
        for (int t = 0; t < 3; t++) {
            const float* src = srcs[t] + s_kk * DD + s_d4 * 4;
            unsigned int da = (unsigned int)__cvta_generic_to_shared(
                &wbuf[0][t][s_kk][s_d4 * 4]);
            asm volatile("cp.async.cg.shared.global [%0], [%1], 16;"
                         :: "r"(da), "l"(src) : "memory");
        }
        asm volatile("cp.async.commit_group;" ::: "memory");

        unsigned long long bK = *(const unsigned long long*)&Kb[t0 * DD + d0];
        unsigned long long bQ = *(const unsigned long long*)&Qb[t0 * DD + d0];
        unsigned long long bV = *(const unsigned long long*)&Vb[t0 * DD + d0];
        unsigned long long bS = *(const unsigned long long*)&g_bsp[d0];
        unsigned long long aK[4], aQ[4], aV[4], aS[4];
#pragma unroll
        for (int j = 0; j < 4; j++) { aK[j] = bK; aQ[j] = bQ; aV[j] = bV; aS[j] = bS; }

        for (int tile = 0; tile < NT; tile++) {
            if (tile + 1 < NT) {
                int stg = (tile + 1) & 1;
#pragma unroll
                for (int t = 0; t < 3; t++) {
                    const float* src = srcs[t] + ((tile + 1) * KT + s_kk) * DD + s_d4 * 4;
                    unsigned int da = (unsigned int)__cvta_generic_to_shared(
                        &wbuf[stg][t][s_kk][s_d4 * 4]);
                    asm volatile("cp.async.cg.shared.global [%0], [%1], 16;"
                                 :: "r"(da), "l"(src) : "memory");
                }
                asm volatile("cp.async.commit_group;" ::: "memory");
                asm volatile("cp.async.wait_group 1;" ::: "memory");
            } else {
                asm volatile("cp.async.wait_group 0;" ::: "memory");
            }
            __syncthreads();
            int cur = tile & 1;
#pragma unroll
            for (int kk = 0; kk < KT; kk++) {
                int k = tile * KT + kk;
                unsigned long long wk = *(const unsigned long long*)&wbuf[cur][0][kk][d0];
                unsigned long long wq = *(const unsigned long long*)&wbuf[cur][1][kk][d0];
                unsigned long long wv = *(const unsigned long long*)&wbuf[cur][2][kk][d0];
                unsigned long long ws = *(const unsigned long long*)&g_Wsp[k * DD + d0];
                float4 xq = *(const float4*)&xsN[k][jb];
                unsigned long long x0 = pack2(xq.x, xq.x);
                unsigned long long x1 = pack2(xq.y, xq.y);
                unsigned long long x2 = pack2(xq.z, xq.z);
                unsigned long long x3 = pack2(xq.w, xq.w);
                fma2(aK[0], x0, wk); fma2(aQ[0], x0, wq); fma2(aV[0], x0, wv); fma2(aS[0], x0, ws);
                fma2(aK[1], x1, wk); fma2(aQ[1], x1, wq); fma2(aV[1], x1, wv); fma2(aS[1], x1, ws);
                fma2(aK[2], x2, wk); fma2(aQ[2], x2, wq); fma2(aV[2], x2, wv); fma2(aS[2], x2, ws);
                fma2(aK[3], x3, wk); fma2(aQ[3], x3, wq); fma2(aV[3], x3, wv); fma2(aS[3], x3, ws);
            }
            __syncthreads();
        }

#pragma unroll
        for (int j = 0; j < 4; j++) {
            int nd = nodes_s[jb + j];
            float lo, hi;
            if (nd >= 0) {
                unpack2(aK[j], lo, hi);
                *(float2*)&g_k [nd * DD + d0] = make_float2(lo, hi);
                unpack2(aV[j], lo, hi);
                *(float2*)&g_v [nd * DD + d0] = make_float2(lo, hi);
                unpack2(aS[j], lo, hi);
                *(float2*)&g_sp[nd * DD + d0] = make_float2(lo, hi);
            }
        }
        // reuse xsN as q storage (all x reads done; barrier above after last tile)
#pragma unroll
        for (int j = 0; j < 4; j++) {
            float lo, hi;
            unpack2(aQ[j], lo, hi);
            xsN[d0][jb + j]     = lo;
            xsN[d0 + 1][jb + j] = hi;
        }
    } else {
        // rare mixed-type block: scalar per node
        for (int j = 0; j < 4; j++) {
            int nd = nodes_s[jb + j];
            int t  = types_s[jb + j];
            float2 aK = *(const float2*)&Kb[t * DD + d0];
            float2 aQ = *(const float2*)&Qb[t * DD + d0];
            float2 aV = *(const float2*)&Vb[t * DD + d0];
            float2 aS = *(const float2*)&g_bsp[d0];
            for (int k = 0; k < DD; k++) {
                float xv = xsN[k][jb + j];
                float2 wk = *(const float2*)&Kw[(t * DD + k) * DD + d0];
                float2 wq = *(const float2*)&Qw[(t * DD + k) * DD + d0];
                float2 wv = *(const float2*)&Vw[(t * DD + k) * DD + d0];
                float2 ws = *(const float2*)&g_Wsp[k * DD + d0];
                aK.x += xv * wk.x; aK.y += xv * wk.y;
                aQ.x += xv * wq.x; aQ.y += xv * wq.y;
                aV.x += xv * wv.x; aV.y += xv * wv.y;
                aS.x += xv * ws.x; aS.y += xv * ws.y;
            }
            if (nd >= 0) {
                *(float2*)&g_k [nd * DD + d0] = aK;
                *(float2*)&g_v [nd * DD + d0] = aV;
                *(float2*)&g_sp[nd * DD + d0] = aS;
            }
            __syncthreads();   // uniform within block (branch is block-uniform)
            xsN[d0][jb + j]     = aQ.x;
            xsN[d0 + 1][jb + j] = aQ.y;
        }
    }
    __syncthreads();

    // q' per relation: qt pair (dk0,dk1) = sum_f q(h,f) * RattPair
    int h   = d0 >> 4;
    int dkp = (d0 >> 1) & 7;
    const unsigned long long* rp = g_Rp + (h * 8 + dkp) * DKK;
#pragma unroll
    for (int r = 0; r < RR; r++) {
        unsigned long long a0 = 0, a1 = 0, a2 = 0, a3 = 0;
#pragma unroll
        for (int f = 0; f < DKK; f++) {
            unsigned long long w = rp[(r * HH * 8) * DKK + f];
            float4 qf = *(const float4*)&xsN[(h << 4) + f][jb];
            fma2(a0, pack2(qf.x, qf.x), w);
            fma2(a1, pack2(qf.y, qf.y), w);
            fma2(a2, pack2(qf.z, qf.z), w);
            fma2(a3, pack2(qf.w, qf.w), w);
        }
        unsigned long long av[4] = {a0, a1, a2, a3};
#pragma unroll
        for (int j = 0; j < 4; j++) {
            int nd = nodes_s[jb + j];
            if (nd >= 0) {
                float lo, hi;
                unpack2(av[j], lo, hi);
                *(float2*)&g_qt[(nd * RR + r) * DD + d0] = make_float2(lo, hi);
            }
        }
    }
}

// ------------------------------ edge setup ------------------------------------
__global__ void k_edgestats(const int* __restrict__ ei, const int* __restrict__ et, int e) {
    int i = blockIdx.x * blockDim.x + threadIdx.x;
    if (i >= e) return;
    int tgt = ei[e + i];
    int r   = et[i];
    atomicAdd(&g_thist[tgt * RR + r], 1);
    if (r == 0) atomicMax(&g_win[ei[i]], i);
}

__global__ void k_scan1(int n4) {
    __shared__ int buf[1024];
    int t = threadIdx.x;
    int gid = blockIdx.x * 1024 + t;
    int v = (gid < n4) ? g_thist[gid] : 0;
    buf[t] = v;
    __syncthreads();
    for (int off = 1; off < 1024; off <<= 1) {
        int x = (t >= off) ? buf[t - off] : 0;
        __syncthreads();
        buf[t] += x;
        __syncthreads();
    }
    if (gid < n4) g_toff[gid] = buf[t] - v;
    if (t == 1023) g_bsum[blockIdx.x] = buf[t];
}

__global__ void k_scan2(int nblocks, int n4) {
    if (threadIdx.x == 0) {
        int run = 0;
        for (int b = 0; b < nblocks; b++) { int x = g_bsum[b]; g_bsum[b] = run; run += x; }
        g_toff[n4] = run;
    }
}

__global__ void k_scan3(int n4) {
    int gid = blockIdx.x * blockDim.x + threadIdx.x;
    if (gid < n4) {
        int v = g_toff[gid] + g_bsum[gid >> 10];
        g_toff[gid] = v;
        g_tcur[gid] = v;
    }
}

__global__ void k_scatter_edges(const int* __restrict__ ei, const int* __restrict__ et,
                                const int* __restrict__ ntype, int e) {
    int i = blockIdx.x * blockDim.x + threadIdx.x;
    if (i >= e) return;
    int src = ei[i];
    int tgt = ei[e + i];
    int r   = et[i];
    int st  = ntype[src];
    int pos = atomicAdd(&g_tcur[tgt * RR + r], 1);
    g_epack[pos] = src | (st << 16);
}

// ------- attention: warp per target, per-relation sub-loops --------------------
__global__ void __launch_bounds__(256)
k_attn(const int* __restrict__ ntype, const float* __restrict__ pri,
       const float* __restrict__ Rmsg, int n) {
    __shared__ float accsh[8][RR][DD];
    int warp = threadIdx.x >> 5, lane = threadIdx.x & 31;
    int i = blockIdx.x * 8 + warp;
    if (i >= n) return;
    int d0 = lane * 4;
    int h  = lane >> 2;

    int tt = ntype[i];
    float p0[TT], p1[TT], p2[TT], p3[TT];
#pragma unroll
    for (int st = 0; st < TT; st++) {
        p0[st] = pri[((tt * RR + 0) * TT + st) * HH + h];
        p1[st] = pri[((tt * RR + 1) * TT + st) * HH + h];
        p2[st] = pri[((tt * RR + 2) * TT + st) * HH + h];
        p3[st] = pri[((tt * RR + 3) * TT + st) * HH + h];
    }

    float den = 0.f;
    float4 acc[RR];
#pragma unroll
    for (int r = 0; r < RR; r++) acc[r] = make_float4(0.f, 0.f, 0.f, 0.f);

#pragma unroll
    for (int r = 0; r < RR; r++) {
        int beg = g_toff[i * RR + r], end = g_toff[i * RR + r + 1];
        if (beg == end) continue;
        float4 qtr = *(const float4*)&g_qt[(i * RR + r) * DD + d0];
        float4 a = make_float4(0.f, 0.f, 0.f, 0.f);
        for (int idx = beg; idx < end; idx++) {
            int pk  = g_epack[idx];
            int src = pk & 0xFFFF;
            int st  = pk >> 16;
            const float4 k4 = *(const float4*)&g_k[src * DD + d0];
            float s = qtr.x * k4.x + qtr.y * k4.y + qtr.z * k4.z + qtr.w * k4.w;
            s += __shfl_xor_sync(0xffffffffu, s, 1);
            s += __shfl_xor_sync(0xffffffffu, s, 2);
            float pr = (r == 0) ? p0[0] : (r == 1) ? p1[0] : (r == 2) ? p2[0] : p3[0];
            if (st == 1) pr = (r == 0) ? p0[1] : (r == 1) ? p1[1] : (r == 2) ? p2[1] : p3[1];
            if (st == 2) pr = (r == 0) ? p0[2] : (r == 1) ? p1[2] : (r == 2) ? p2[2] : p3[2];
            float pe = __expf(s * pr * 0.25f);
            den += pe;
            const float4 v4 = *(const float4*)&g_v[src * DD + d0];
            a.x += pe * v4.x;
            a.y += pe * v4.y;
            a.z += pe * v4.z;
            a.w += pe * v4.w;
        }
        acc[r] = a;
    }

    float inv = 1.f / (den + 1e-16f);
#pragma unroll
    for (int r = 0; r < RR; r++) {
        accsh[warp][r][d0 + 0] = acc[r].x * inv;
        accsh[warp][r][d0 + 1] = acc[r].y * inv;
        accsh[warp][r][d0 + 2] = acc[r].z * inv;
        accsh[warp][r][d0 + 3] = acc[r].w * inv;
    }
    __syncwarp();

    int f0 = (lane & 3) * 4;
    float4 o = make_float4(0.f, 0.f, 0.f, 0.f);
#pragma unroll
    for (int r = 0; r < RR; r++) {
#pragma unroll 4
        for (int dk = 0; dk < DKK; dk++) {
            float a = accsh[warp][r][(h << 4) + dk];
            const float4 w = *(const float4*)&Rmsg[(((r * HH + h) * DKK + dk) * DKK) + f0];
            o.x += a * w.x;
            o.y += a * w.y;
            o.z += a * w.z;
            o.w += a * w.w;
        }
    }
    *(float4*)&g_aggr[i * DD + d0] = o;
}

// ------------- final: speaker add + GELU + per-type A projection + skip -------
__global__ void __launch_bounds__(256, 3)
k_final(const float* __restrict__ x, const int* __restrict__ ntype,
        const int* __restrict__ ei,
        const float* __restrict__ Aw, const float* __restrict__ Ab,
        const float* __restrict__ skip, float* __restrict__ out, int n, int e) {
    __shared__ __align__(16) float gsN[DD][GST];
    __shared__ int nodes_s[NPB], types_s[NPB], spsrc_s[NPB];
    int tid  = threadIdx.x;
    int base = blockIdx.x * NPB;
    if (tid < NPB) {
        int idx = base + tid;
        int cidx = (idx < n) ? idx : (n - 1);
        int nd = (idx < n) ? g_perm[idx] : -1;
        nodes_s[tid] = nd;
        types_s[tid] = ntype[g_perm[cidx]];
        int sps = -1;
        if (nd >= 0) {
            int we = g_win[nd];
            if (we >= 0) sps = ei[e + we];
        }
        spsrc_s[tid] = sps;
    }
    __syncthreads();

    for (int idx = tid; idx < NPB * DD; idx += 256) {
        int j = idx >> 7;
        int k = idx & 127;
        int nd = nodes_s[j];
        float v = 0.f;
        if (nd >= 0) {
            v = g_aggr[nd * DD + k];
            int sps = spsrc_s[j];
            if (sps >= 0) v += g_sp[sps * DD + k];
            v = 0.5f * v * (1.f + erff(v * 0.70710678118654752f));
        }
        gsN[k][j] = v;
    }
    __syncthreads();

    int g  = tid >> 6;
    int p  = tid & 63;
    int d0 = 2 * p;
    int jb = g * 8;

    int t0 = types_s[0];
    bool uniform = true;
#pragma unroll
    for (int j = 1; j < NPB; j++) uniform &= (types_s[j] == t0);

    if (uniform) {
        const float* pA = Aw + t0 * DD * DD + d0;
        unsigned long long bA = *(const unsigned long long*)&Ab[t0 * DD + d0];
        unsigned long long aA[8];
#pragma unroll
        for (int j = 0; j < 8; j++) aA[j] = bA;
#pragma unroll 4
        for (int k = 0; k < DD; k++) {
            unsigned long long w2 = *(const unsigned long long*)&pA[k * DD];
            float4 q0 = *(const float4*)&gsN[k][jb];
            float4 q1 = *(const float4*)&gsN[k][jb + 4];
            fma2(aA[0], pack2(q0.x, q0.x), w2);
            fma2(aA[1], pack2(q0.y, q0.y), w2);
            fma2(aA[2], pack2(q0.z, q0.z), w2);
            fma2(aA[3], pack2(q0.w, q0.w), w2);
            fma2(aA[4], pack2(q1.x, q1.x), w2);
            fma2(aA[5], pack2(q1.y, q1.y), w2);
            fma2(aA[6], pack2(q1.z, q1.z), w2);
            fma2(aA[7], pack2(q1.w, q1.w), w2);
        }
        float sk = skip[t0];
        float alpha = 1.f / (1.f + __expf(-sk));
        float beta  = 1.f - alpha;
#pragma unroll
        for (int j = 0; j < 8; j++) {
            int nd = nodes_s[jb + j];
            if (nd < 0) continue;
            float lo, hi;
            unpack2(aA[j], lo, hi);
            float2 xv = *(const float2*)&x[nd * DD + d0];
            *(float2*)&out[nd * DD + d0] =
                make_float2(lo * alpha + xv.x * beta, hi * alpha + xv.y * beta);
        }
    } else {
        for (int j = 0; j < 8; j++) {
            int nd = nodes_s[jb + j];
            if (nd < 0) continue;
            int t = types_s[jb + j];
            float2 aA = *(const float2*)&Ab[t * DD + d0];
            for (int k = 0; k < DD; k++) {
                float gv = gsN[k][jb + j];
                float2 w = *(const float2*)&Aw[(t * DD + k) * DD + d0];
                aA.x += gv * w.x; aA.y += gv * w.y;
            }
            float sk = skip[t];
            float alpha = 1.f / (1.f + __expf(-sk));
            float beta  = 1.f - alpha;
            float2 xv = *(const float2*)&x[nd * DD + d0];
            *(float2*)&out[nd * DD + d0] =
                make_float2(aA.x * alpha + xv.x * beta, aA.y * alpha + xv.y * beta);
        }
    }
}

// --------------------------------- launcher -----------------------------------
extern "C" void kernel_launch(void* const* d_in, const int* in_sizes, int n_in,
                              void* d_out, int out_size) {
    const float* node_inp  = (const float*)d_in[0];
    const int*   node_type = (const int*)  d_in[1];
    const int*   edge_index= (const int*)  d_in[2];
    const int*   edge_type = (const int*)  d_in[3];
    const float* Kw = (const float*)d_in[5];
    const float* Kb = (const float*)d_in[6];
    const float* Qw = (const float*)d_in[7];
    const float* Qb = (const float*)d_in[8];
    const float* Vw = (const float*)d_in[9];
    const float* Vb = (const float*)d_in[10];
    const float* Aw = (const float*)d_in[11];
    const float* Ab = (const float*)d_in[12];
    const float* pri  = (const float*)d_in[13];
    const float* Ratt = (const float*)d_in[14];
    const float* Rmsg = (const float*)d_in[15];
    const float* s2u  = (const float*)d_in[16];
    const float* skip = (const float*)d_in[17];
    float* out = (float*)d_out;

    int n = in_sizes[1];
    int e = in_sizes[3];
    if (n > NMAX) n = NMAX;
    if (e > EMAX) e = EMAX;
    int n4 = n * RR;

    int nb  = (n + 255) / 256;
    int n4b = (n4 + 255) / 256;
    int eb  = (e + 255) / 256;
    int sb  = (n4 + 1023) / 1024;

    k_init<<<n4b + 65 + 16, 256>>>(Vw, Vb, s2u, Ratt, n, n4b);
    k_nodehist<<<nb, 256>>>(node_type, n);
    k_nodescatter<<<nb, 256>>>(node_type, n);
    k_proj<<<(n + NPP - 1) / NPP, 256>>>(node_inp, node_type, Kw, Kb, Qw, Qb,
                                         Vw, Vb, n);
    k_edgestats<<<eb, 256>>>(edge_index, edge_type, e);
    k_scan1<<<sb, 1024>>>(n4);
    k_scan2<<<1, 32>>>(sb, n4);
    k_scan3<<<n4b, 256>>>(n4);
    k_scatter_edges<<<eb, 256>>>(edge_index, edge_type, node_type, e);
    k_attn<<<(n + 7) / 8, 256>>>(node_type, pri, Rmsg, n);
    k_final<<<(n + NPB - 1) / NPB, 256>>>(node_inp, node_type, edge_index,
                                          Aw, Ab, skip, out, n, e);
}